// round 15
// baseline (speedup 1.0000x reference)
#include <cuda_runtime.h>
#include <cstdint>

#define N_NODES 262144
#define DIM     256
#define HID     128
#define NGRAPH  2048
#define NTILES  2048          // N_NODES / 128
#define SGRID   152
#define NTHR    512
#define CHUNK   256           // rows per stream_pool block
#define PBLK    (N_NODES / CHUNK)   // 1024

// smem layout for score kernel
#define WSF_BYTES   131072    // uint32 wsf[32 ksteps][16 ntiles][32 lanes][2]
#define XS_OFF      131072    // float xs[2][128][36] = 36864 B
#define B1F_OFF     167936    // float b1f[16][32][2] = 4096 B
#define W2F_OFF     172032    // 4096 B
#define SCP_OFF     176128    // float scp[4][128] = 2048 B
#define SMEM_BYTES  178176

__device__ float g_scores[N_NODES];
__device__ float g_M[NGRAPH];
__device__ float g_invS[NGRAPH];

// ---------------------------------------------------------------------------
__device__ __forceinline__ uint32_t f2tf32(float f) {
    uint32_t u;
    asm("cvt.rna.tf32.f32 %0, %1;" : "=r"(u) : "f"(f));
    return u;
}

__device__ __forceinline__ void mma_tf32(float* c,
                                         uint32_t a0, uint32_t a1, uint32_t a2, uint32_t a3,
                                         uint32_t b0, uint32_t b1) {
    asm volatile(
        "mma.sync.aligned.m16n8k8.row.col.f32.tf32.tf32.f32 "
        "{%0,%1,%2,%3}, {%4,%5,%6,%7}, {%8,%9}, {%0,%1,%2,%3};"
        : "+f"(c[0]), "+f"(c[1]), "+f"(c[2]), "+f"(c[3])
        : "r"(a0), "r"(a1), "r"(a2), "r"(a3), "r"(b0), "r"(b1));
}

__device__ __forceinline__ void cp16(uint32_t dst, const void* src) {
    asm volatile("cp.async.cg.shared.global [%0], [%1], 16;" :: "r"(dst), "l"(src));
}
#define CP_COMMIT() asm volatile("cp.async.commit_group;")
#define CP_WAIT1()  asm volatile("cp.async.wait_group 1;")

__device__ __forceinline__ int lower_bound_i(const int* __restrict__ b, int n, int key) {
    int lo = 0, hi = n;
    while (lo < hi) {
        int mid = (lo + hi) >> 1;
        if (b[mid] < key) lo = mid + 1; else hi = mid;
    }
    return lo;
}
__device__ __forceinline__ float warp_max(float v) {
    #pragma unroll
    for (int o = 16; o; o >>= 1) v = fmaxf(v, __shfl_xor_sync(0xffffffffu, v, o));
    return v;
}
__device__ __forceinline__ float warp_sum(float v) {
    #pragma unroll
    for (int o = 16; o; o >>= 1) v += __shfl_xor_sync(0xffffffffu, v, o);
    return v;
}

// ---------------------------------------------------------------------------
// stage one x chunk (128 rows x 32 k-floats, 16 KB) into xs[slot] via cp.async
// (512 threads -> 2 x 16B each)
// ---------------------------------------------------------------------------
__device__ __forceinline__ void stage_chunk(const float* __restrict__ x,
                                            int tile, int kc, int slot,
                                            int tid, uint32_t xs_u32) {
    #pragma unroll
    for (int i = 0; i < 2; i++) {
        int j = tid + NTHR * i;         // 0..1023
        int row = j >> 3;               // 0..127
        int col = (j & 7) * 4;          // 0..28
        const float* src = x + (size_t)(tile * 128 + row) * DIM + kc * 32 + col;
        uint32_t dst = xs_u32 + (uint32_t)(slot * (128 * 36) + row * 36 + col) * 4u;
        cp16(dst, src);
    }
}

// ---------------------------------------------------------------------------
// Kernel 1: scores[i] = b2 + sum_j W2[j] * relu(b1[j] + sum_k x[i][k]*W1[k][j])
// 512 threads = 16 warps = 4 row-groups x 4 col-groups; each warp 32 rows x
// 32 cols (2 mt x 4 nt, 32 accum regs). Twice the warps of R14 to hide
// LDS->MMA latency (tensor-busy floor ~57us; goal is utilization).
// ---------------------------------------------------------------------------
__global__ void __launch_bounds__(NTHR, 1)
score_kernel(const float* __restrict__ x,
             const float* __restrict__ W1,
             const float* __restrict__ b1,
             const float* __restrict__ W2,
             const float* __restrict__ b2) {
    extern __shared__ __align__(16) unsigned char smem[];
    uint32_t* wsf = (uint32_t*)smem;                      // [ks][nt][lane][2]
    float*    xs  = (float*)(smem + XS_OFF);              // [2][128][36]
    float*    b1f = (float*)(smem + B1F_OFF);             // [nt][lane][2]
    float*    w2f = (float*)(smem + W2F_OFF);
    float*    scp = (float*)(smem + SCP_OFF);             // [4][128]
    const uint32_t xs_u32 = (uint32_t)__cvta_generic_to_shared(xs);

    const int tid  = threadIdx.x;
    const int lane = tid & 31;
    const int warp = tid >> 5;
    const int rg   = warp >> 2;       // row-group 0..3 (32 rows each)
    const int cg   = warp & 3;        // col-group 0..3 (32 cols each)

    // --- stage W1 as tf32 B-fragments: b0 = W1[ks*8 + (lane&3)][nt*8 + lane/4]
    for (int i = tid; i < 32 * 16 * 32; i += NTHR) {
        int l = i & 31, nt = (i >> 5) & 15, ks = i >> 9;
        int col = nt * 8 + (l >> 2);
        int r0  = ks * 8 + (l & 3);
        wsf[2 * i + 0] = f2tf32(W1[r0 * HID + col]);
        wsf[2 * i + 1] = f2tf32(W1[(r0 + 4) * HID + col]);
    }
    // --- stage b1 / W2 in C-fragment column order: cols nt*8 + 2*(lane&3) {,+1}
    for (int i = tid; i < 16 * 32; i += NTHR) {
        int l = i & 31, nt = i >> 5;
        int c0 = nt * 8 + 2 * (l & 3);
        b1f[2 * i + 0] = b1[c0];
        b1f[2 * i + 1] = b1[c0 + 1];
        w2f[2 * i + 0] = W2[c0];
        w2f[2 * i + 1] = W2[c0 + 1];
    }
    const float b2v = b2[0];

    // --- prologue: chunk 0 of first tile into buffer 0
    stage_chunk(x, blockIdx.x, 0, 0, tid, xs_u32);
    CP_COMMIT();
    __syncthreads();

    const int rA = rg * 32 + (lane >> 2);     // A-frag base row (mt adds 16*mt)
    const int t4 = lane & 3;

    for (int tile = blockIdx.x; tile < NTILES; tile += SGRID) {
        float c[2][4][4];
        #pragma unroll
        for (int mt = 0; mt < 2; mt++)
            #pragma unroll
            for (int nt = 0; nt < 4; nt++)
                #pragma unroll
                for (int q = 0; q < 4; q++) c[mt][nt][q] = 0.0f;

        #pragma unroll 1
        for (int kc = 0; kc < 8; kc++) {
            const int slot = kc & 1;
            // prefetch next chunk into other buffer
            int ptile = (kc < 7) ? tile : (tile + SGRID);
            int pkc   = (kc + 1) & 7;
            if (ptile < NTILES)
                stage_chunk(x, ptile, pkc, slot ^ 1, tid, xs_u32);
            CP_COMMIT();
            CP_WAIT1();              // current chunk resident
            __syncthreads();

            const float* xb = xs + slot * (128 * 36);
            #pragma unroll
            for (int ksl = 0; ksl < 4; ksl++) {
                const int k0 = ksl * 8;
                const int ks = kc * 4 + ksl;

                // B fragments for this warp's 4 nts (LDS.64 each)
                const uint32_t* wb = wsf + (ks * 512 + lane) * 2;
                uint2 bf[4];
                #pragma unroll
                for (int nt = 0; nt < 4; nt++)
                    bf[nt] = *(const uint2*)(wb + (cg * 4 + nt) * 64);

                // A fragments for 2 mtiles
                uint32_t a[2][4];
                const float* rp = xb + rA * 36 + k0 + t4;
                #pragma unroll
                for (int mt = 0; mt < 2; mt++) {
                    const float* mp = rp + mt * 16 * 36;
                    a[mt][0] = f2tf32(mp[0]);
                    a[mt][1] = f2tf32(mp[8 * 36]);
                    a[mt][2] = f2tf32(mp[4]);
                    a[mt][3] = f2tf32(mp[8 * 36 + 4]);
                }

                #pragma unroll
                for (int mt = 0; mt < 2; mt++)
                    #pragma unroll
                    for (int nt = 0; nt < 4; nt++)
                        mma_tf32(c[mt][nt], a[mt][0], a[mt][1], a[mt][2], a[mt][3],
                                 bf[nt].x, bf[nt].y);
            }
            __syncthreads();
        }

        // --- epilogue: bias + relu + dot with W2 over this warp's 32 cols ---
        #pragma unroll
        for (int mt = 0; mt < 2; mt++) {
            float p0 = 0.0f, p8 = 0.0f;
            #pragma unroll
            for (int nt = 0; nt < 4; nt++) {
                int bi = ((cg * 4 + nt) * 32 + lane) * 2;
                float q0 = b1f[bi], q1 = b1f[bi + 1];
                float w0 = w2f[bi], w1 = w2f[bi + 1];
                p0 += fmaxf(c[mt][nt][0] + q0, 0.0f) * w0 + fmaxf(c[mt][nt][1] + q1, 0.0f) * w1;
                p8 += fmaxf(c[mt][nt][2] + q0, 0.0f) * w0 + fmaxf(c[mt][nt][3] + q1, 0.0f) * w1;
            }
            p0 += __shfl_xor_sync(0xffffffffu, p0, 1);
            p0 += __shfl_xor_sync(0xffffffffu, p0, 2);
            p8 += __shfl_xor_sync(0xffffffffu, p8, 1);
            p8 += __shfl_xor_sync(0xffffffffu, p8, 2);
            if ((lane & 3) == 0) {
                int row = rg * 32 + mt * 16 + (lane >> 2);
                scp[cg * 128 + row]     = p0;
                scp[cg * 128 + row + 8] = p8;
            }
        }
        __syncthreads();
        if (tid < 128)
            g_scores[tile * 128 + tid] =
                scp[tid] + scp[128 + tid] + scp[256 + tid] + scp[384 + tid] + b2v;
        __syncthreads();
    }
}

// ---------------------------------------------------------------------------
// Kernel 2: per-graph softmax stats (max, 1/sum_exp); also zero out[].
// ---------------------------------------------------------------------------
__global__ void __launch_bounds__(256)
stats_kernel(const int* __restrict__ batch, float* __restrict__ out) {
    const int g = blockIdx.x;
    const int tid = threadIdx.x;
    const int lane = tid & 31, wid = tid >> 5;
    __shared__ int sse[2];
    __shared__ float red[8];

    out[g * DIM + tid] = 0.0f;

    if (tid < 2) sse[tid] = lower_bound_i(batch, N_NODES, g + tid);
    __syncthreads();
    const int start = sse[0], end = sse[1];

    float m = -1e30f;
    for (int i = start + tid; i < end; i += 256) m = fmaxf(m, g_scores[i]);
    m = warp_max(m);
    if (lane == 0) red[wid] = m;
    __syncthreads();
    if (wid == 0) {
        float v = (lane < 8) ? red[lane] : -1e30f;
        v = warp_max(v);
        if (lane == 0) red[0] = v;
    }
    __syncthreads();
    const float M = red[0];
    __syncthreads();

    float s = 0.0f;
    for (int i = start + tid; i < end; i += 256) s += __expf(g_scores[i] - M);
    s = warp_sum(s);
    if (lane == 0) red[wid] = s;
    __syncthreads();
    if (wid == 0) {
        float v = (lane < 8) ? red[lane] : 0.0f;
        v = warp_sum(v);
        if (lane == 0) {
            g_M[g] = M;
            g_invS[g] = (end > start) ? (1.0f / v) : 0.0f;
        }
    }
}

// ---------------------------------------------------------------------------
// Kernel 3: streaming weighted pooling (uniform chunks, atomic boundary flush).
// Blocks walk x in REVERSE address order for L2 tail reuse from score_kernel.
// ---------------------------------------------------------------------------
__global__ void __launch_bounds__(256)
stream_pool(const int* __restrict__ batch,
            const float* __restrict__ x,
            float* __restrict__ out) {
    const int base = (PBLK - 1 - blockIdx.x) * CHUNK;
    const int tid = threadIdx.x;
    __shared__ __align__(16) float sw[CHUNK];
    __shared__ int sb[CHUNK];

    {
        int r = base + tid;
        int b = batch[r];
        sb[tid] = b;
        sw[tid] = __expf(g_scores[r] - g_M[b]) * g_invS[b];
    }
    __syncthreads();

    const int c4 = (tid & 63) * 4;
    const int rg = tid >> 6;
    const float* xp0 = x + (size_t)base * DIM + c4;

    float4 a0 = make_float4(0.f, 0.f, 0.f, 0.f);
    float4 a1 = make_float4(0.f, 0.f, 0.f, 0.f);
    float4 a2 = make_float4(0.f, 0.f, 0.f, 0.f);
    float4 a3 = make_float4(0.f, 0.f, 0.f, 0.f);
    int cur = sb[rg];

    #define FLUSH_ACC() do {                                             \
        float fx = (a0.x + a1.x) + (a2.x + a3.x);                        \
        float fy = (a0.y + a1.y) + (a2.y + a3.y);                        \
        float fz = (a0.z + a1.z) + (a2.z + a3.z);                        \
        float fw = (a0.w + a1.w) + (a2.w + a3.w);                        \
        float* op = out + (size_t)cur * DIM + c4;                        \
        atomicAdd(op + 0, fx); atomicAdd(op + 1, fy);                    \
        atomicAdd(op + 2, fz); atomicAdd(op + 3, fw);                    \
        a0 = a1 = a2 = a3 = make_float4(0.f, 0.f, 0.f, 0.f);             \
    } while (0)

    #pragma unroll 1
    for (int j = rg; j < CHUNK; j += 16) {
        if (sb[j + 12] == cur) {
            float w0 = sw[j], w1 = sw[j + 4], w2 = sw[j + 8], w3 = sw[j + 12];
            float4 v0 = *(const float4*)(xp0 + (size_t)j * DIM);
            float4 v1 = *(const float4*)(xp0 + (size_t)(j + 4) * DIM);
            float4 v2 = *(const float4*)(xp0 + (size_t)(j + 8) * DIM);
            float4 v3 = *(const float4*)(xp0 + (size_t)(j + 12) * DIM);
            a0.x = fmaf(w0, v0.x, a0.x); a0.y = fmaf(w0, v0.y, a0.y);
            a0.z = fmaf(w0, v0.z, a0.z); a0.w = fmaf(w0, v0.w, a0.w);
            a1.x = fmaf(w1, v1.x, a1.x); a1.y = fmaf(w1, v1.y, a1.y);
            a1.z = fmaf(w1, v1.z, a1.z); a1.w = fmaf(w1, v1.w, a1.w);
            a2.x = fmaf(w2, v2.x, a2.x); a2.y = fmaf(w2, v2.y, a2.y);
            a2.z = fmaf(w2, v2.z, a2.z); a2.w = fmaf(w2, v2.w, a2.w);
            a3.x = fmaf(w3, v3.x, a3.x); a3.y = fmaf(w3, v3.y, a3.y);
            a3.z = fmaf(w3, v3.z, a3.z); a3.w = fmaf(w3, v3.w, a3.w);
        } else {
            #pragma unroll
            for (int t = 0; t < 4; t++) {
                int jj = j + 4 * t;
                int b = sb[jj];
                if (b != cur) { FLUSH_ACC(); cur = b; }
                float w = sw[jj];
                float4 v = *(const float4*)(xp0 + (size_t)jj * DIM);
                a0.x = fmaf(w, v.x, a0.x); a0.y = fmaf(w, v.y, a0.y);
                a0.z = fmaf(w, v.z, a0.z); a0.w = fmaf(w, v.w, a0.w);
            }
        }
    }
    FLUSH_ACC();
    #undef FLUSH_ACC
}

// ---------------------------------------------------------------------------
extern "C" void kernel_launch(void* const* d_in, const int* in_sizes, int n_in,
                              void* d_out, int out_size) {
    const float* x     = (const float*)d_in[0];
    const int*   batch = (const int*)d_in[1];
    // d_in[2] = num_graphs (constant 2048, unused)
    const float* W1 = (const float*)d_in[3];
    const float* b1 = (const float*)d_in[4];
    const float* W2 = (const float*)d_in[5];
    const float* b2 = (const float*)d_in[6];
    float* out = (float*)d_out;

    cudaFuncSetAttribute(score_kernel, cudaFuncAttributeMaxDynamicSharedMemorySize, SMEM_BYTES);
    score_kernel<<<SGRID, NTHR, SMEM_BYTES>>>(x, W1, b1, W2, b2);
    stats_kernel<<<NGRAPH, 256>>>(batch, out);
    stream_pool<<<PBLK, 256>>>(batch, x, out);
}

// round 16
// speedup vs baseline: 1.4290x; 1.4290x over previous
#include <cuda_runtime.h>
#include <cuda_fp16.h>
#include <cstdint>

#define N_NODES 262144
#define DIM     256
#define HID     128
#define NGRAPH  2048
#define NTILES  2048          // N_NODES / 128
#define SGRID   304           // 2 CTAs per SM
#define CHUNK   256           // rows per stream_pool block
#define PBLK    (N_NODES / CHUNK)   // 1024

// smem layout for score kernel (fp16 fragments)
#define WSF_BYTES   65536     // uint32 wsf[16 ks][16 nt][32 lanes][2]  (half2 pairs)
#define XS_OFF      65536     // uint32 xs[2][128][20] = 20480 B (16 data half2 + pad4)
#define B1F_OFF     86016     // float b1f[16][32][2] = 4096 B
#define W2F_OFF     90112     // 4096 B
#define SCP_OFF     94208     // float scp[4][128] = 2048 B
#define SMEM_BYTES  96256

#define XS_STRIDE   20        // uint32 units per row (bank-conflict-free for A frags)

__device__ float g_scores[N_NODES];
__device__ float g_M[NGRAPH];
__device__ float g_invS[NGRAPH];

// ---------------------------------------------------------------------------
__device__ __forceinline__ uint32_t f2h2(float lo, float hi) {
    __half2 h = __floats2half2_rn(lo, hi);
    return *(uint32_t*)&h;
}

__device__ __forceinline__ void mma_f16(float* c,
                                        uint32_t a0, uint32_t a1, uint32_t a2, uint32_t a3,
                                        uint32_t b0, uint32_t b1) {
    asm volatile(
        "mma.sync.aligned.m16n8k16.row.col.f32.f16.f16.f32 "
        "{%0,%1,%2,%3}, {%4,%5,%6,%7}, {%8,%9}, {%0,%1,%2,%3};"
        : "+f"(c[0]), "+f"(c[1]), "+f"(c[2]), "+f"(c[3])
        : "r"(a0), "r"(a1), "r"(a2), "r"(a3), "r"(b0), "r"(b1));
}

__device__ __forceinline__ int lower_bound_i(const int* __restrict__ b, int n, int key) {
    int lo = 0, hi = n;
    while (lo < hi) {
        int mid = (lo + hi) >> 1;
        if (b[mid] < key) lo = mid + 1; else hi = mid;
    }
    return lo;
}
__device__ __forceinline__ float warp_max(float v) {
    #pragma unroll
    for (int o = 16; o; o >>= 1) v = fmaxf(v, __shfl_xor_sync(0xffffffffu, v, o));
    return v;
}
__device__ __forceinline__ float warp_sum(float v) {
    #pragma unroll
    for (int o = 16; o; o >>= 1) v += __shfl_xor_sync(0xffffffffu, v, o);
    return v;
}

// ---------------------------------------------------------------------------
// Kernel 1: scores[i] = b2 + sum_j W2[j] * relu(b1[j] + sum_k x[i][k]*W1[k][j])
// fp16 m16n8k16 mma.sync (same 10-bit mantissa as tf32, 2x MACs/instr, full
// rate). R5 structure: 128-row tiles, 16 rows/warp, 8 warps, register-prefetch
// double buffer with fp32->fp16 convert before STS. 94KB smem -> 2 CTAs/SM.
// ---------------------------------------------------------------------------
__global__ void __launch_bounds__(256, 2)
score_kernel(const float* __restrict__ x,
             const float* __restrict__ W1,
             const float* __restrict__ b1,
             const float* __restrict__ W2,
             const float* __restrict__ b2) {
    extern __shared__ __align__(16) unsigned char smem[];
    uint32_t* wsf = (uint32_t*)smem;                      // [ks][nt][lane][2]
    uint32_t* xs  = (uint32_t*)(smem + XS_OFF);           // [2][128][20]
    float*    b1f = (float*)(smem + B1F_OFF);             // [nt][lane][2]
    float*    w2f = (float*)(smem + W2F_OFF);
    float*    scp = (float*)(smem + SCP_OFF);             // [4][128]

    const int tid  = threadIdx.x;
    const int lane = tid & 31;
    const int warp = tid >> 5;

    // --- stage W1 as fp16 B-fragments for m16n8k16:
    //     b0 = half2(W1[ks*16+2t4][n], W1[ks*16+2t4+1][n])
    //     b1 = half2(W1[ks*16+2t4+8][n], W1[ks*16+2t4+9][n]),  n = nt*8 + l/4
    for (int i = tid; i < 16 * 16 * 32; i += 256) {
        int l = i & 31, nt = (i >> 5) & 15, ks = i >> 9;
        int n  = nt * 8 + (l >> 2);
        int k0 = ks * 16 + 2 * (l & 3);
        wsf[2 * i + 0] = f2h2(W1[k0 * HID + n],       W1[(k0 + 1) * HID + n]);
        wsf[2 * i + 1] = f2h2(W1[(k0 + 8) * HID + n], W1[(k0 + 9) * HID + n]);
    }
    // --- stage b1 / W2 in C-fragment column order: cols nt*8 + 2*(lane&3) {,+1}
    for (int i = tid; i < 16 * 32; i += 256) {
        int l = i & 31, nt = i >> 5;
        int c0 = nt * 8 + 2 * (l & 3);
        b1f[2 * i + 0] = b1[c0];
        b1f[2 * i + 1] = b1[c0 + 1];
        w2f[2 * i + 0] = W2[c0];
        w2f[2 * i + 1] = W2[c0 + 1];
    }
    const float b2v = b2[0];

    const int srow = tid >> 3;        // staging row 0..31 (covers +32q, q=0..3)
    const int scol = (tid & 7) * 4;   // float col offset within 32-wide chunk

    // --- prologue: chunk 0 of first tile into buffer 0 (convert + store)
    {
        int t0 = blockIdx.x;
        if (t0 < NTILES) {
            #pragma unroll
            for (int q = 0; q < 4; q++) {
                int row = srow + 32 * q;
                float4 v = *(const float4*)(x + (size_t)(t0 * 128 + row) * DIM + scol);
                uint2 h = make_uint2(f2h2(v.x, v.y), f2h2(v.z, v.w));
                *(uint2*)(xs + row * XS_STRIDE + (scol >> 1)) = h;
            }
        }
    }
    __syncthreads();

    const int rA = warp * 16 + (lane >> 2);   // A-frag row within tile
    const int t4 = lane & 3;

    for (int tile = blockIdx.x; tile < NTILES; tile += SGRID) {
        float c[16][4];
        #pragma unroll
        for (int nt = 0; nt < 16; nt++)
            #pragma unroll
            for (int q = 0; q < 4; q++) c[nt][q] = 0.0f;

        #pragma unroll 1
        for (int kc = 0; kc < 8; kc++) {
            // prefetch next chunk (next tile's chunk 0 when kc==7)
            int ptile = (kc < 7) ? tile : (tile + SGRID);
            int pkc   = (kc + 1) & 7;
            bool pv   = (ptile < NTILES);
            float4 pr[4];
            if (pv) {
                #pragma unroll
                for (int q = 0; q < 4; q++) {
                    int row = srow + 32 * q;
                    pr[q] = *(const float4*)(x + (size_t)(ptile * 128 + row) * DIM + pkc * 32 + scol);
                }
            }

            // compute 2 k16-steps from current buffer
            const uint32_t* xb = xs + (kc & 1) * (128 * XS_STRIDE);
            #pragma unroll
            for (int ksl = 0; ksl < 2; ksl++) {
                const int cb = ksl * 8 + t4;          // uint32 col base (k0/2 + t4)
                const uint32_t* rp = xb + rA * XS_STRIDE + cb;
                uint32_t a0 = rp[0];
                uint32_t a1 = rp[8 * XS_STRIDE];
                uint32_t a2 = rp[4];
                uint32_t a3 = rp[8 * XS_STRIDE + 4];
                const int ks = kc * 2 + ksl;
                const uint32_t* wb = wsf + (ks * 512 + lane) * 2;
                #pragma unroll
                for (int nt = 0; nt < 16; nt++) {
                    uint2 bf = *(const uint2*)(wb + nt * 64);
                    mma_f16(c[nt], a0, a1, a2, a3, bf.x, bf.y);
                }
            }

            // convert + store prefetched chunk into other buffer
            if (pv) {
                uint32_t* xd = xs + ((kc + 1) & 1) * (128 * XS_STRIDE);
                #pragma unroll
                for (int q = 0; q < 4; q++) {
                    int row = srow + 32 * q;
                    uint2 h = make_uint2(f2h2(pr[q].x, pr[q].y), f2h2(pr[q].z, pr[q].w));
                    *(uint2*)(xd + row * XS_STRIDE + (scol >> 1)) = h;
                }
            }
            __syncthreads();
        }

        // --- epilogue: bias + relu + dot with W2, reduce over j
        float p0 = 0.0f, p8 = 0.0f;
        #pragma unroll
        for (int nt = 0; nt < 16; nt++) {
            int bi = (nt * 32 + lane) * 2;
            float q0 = b1f[bi], q1 = b1f[bi + 1];
            float w0 = w2f[bi], w1 = w2f[bi + 1];
            p0 += fmaxf(c[nt][0] + q0, 0.0f) * w0 + fmaxf(c[nt][1] + q1, 0.0f) * w1;
            p8 += fmaxf(c[nt][2] + q0, 0.0f) * w0 + fmaxf(c[nt][3] + q1, 0.0f) * w1;
        }
        p0 += __shfl_xor_sync(0xffffffffu, p0, 1);
        p0 += __shfl_xor_sync(0xffffffffu, p0, 2);
        p8 += __shfl_xor_sync(0xffffffffu, p8, 1);
        p8 += __shfl_xor_sync(0xffffffffu, p8, 2);
        if ((lane & 3) == 0) {
            int row = tile * 128 + warp * 16 + (lane >> 2);
            g_scores[row]     = p0 + b2v;
            g_scores[row + 8] = p8 + b2v;
        }
    }
}

// ---------------------------------------------------------------------------
// Kernel 2: per-graph softmax stats (max, 1/sum_exp); also zero out[].
// ---------------------------------------------------------------------------
__global__ void __launch_bounds__(256)
stats_kernel(const int* __restrict__ batch, float* __restrict__ out) {
    const int g = blockIdx.x;
    const int tid = threadIdx.x;
    const int lane = tid & 31, wid = tid >> 5;
    __shared__ int sse[2];
    __shared__ float red[8];

    out[g * DIM + tid] = 0.0f;

    if (tid < 2) sse[tid] = lower_bound_i(batch, N_NODES, g + tid);
    __syncthreads();
    const int start = sse[0], end = sse[1];

    float m = -1e30f;
    for (int i = start + tid; i < end; i += 256) m = fmaxf(m, g_scores[i]);
    m = warp_max(m);
    if (lane == 0) red[wid] = m;
    __syncthreads();
    if (wid == 0) {
        float v = (lane < 8) ? red[lane] : -1e30f;
        v = warp_max(v);
        if (lane == 0) red[0] = v;
    }
    __syncthreads();
    const float M = red[0];
    __syncthreads();

    float s = 0.0f;
    for (int i = start + tid; i < end; i += 256) s += __expf(g_scores[i] - M);
    s = warp_sum(s);
    if (lane == 0) red[wid] = s;
    __syncthreads();
    if (wid == 0) {
        float v = (lane < 8) ? red[lane] : 0.0f;
        v = warp_sum(v);
        if (lane == 0) {
            g_M[g] = M;
            g_invS[g] = (end > start) ? (1.0f / v) : 0.0f;
        }
    }
}

// ---------------------------------------------------------------------------
// Kernel 3: streaming weighted pooling (uniform chunks, atomic boundary flush).
// Blocks walk x in REVERSE address order for L2 tail reuse from score_kernel.
// ---------------------------------------------------------------------------
__global__ void __launch_bounds__(256)
stream_pool(const int* __restrict__ batch,
            const float* __restrict__ x,
            float* __restrict__ out) {
    const int base = (PBLK - 1 - blockIdx.x) * CHUNK;
    const int tid = threadIdx.x;
    __shared__ __align__(16) float sw[CHUNK];
    __shared__ int sb[CHUNK];

    {
        int r = base + tid;
        int b = batch[r];
        sb[tid] = b;
        sw[tid] = __expf(g_scores[r] - g_M[b]) * g_invS[b];
    }
    __syncthreads();

    const int c4 = (tid & 63) * 4;
    const int rg = tid >> 6;
    const float* xp0 = x + (size_t)base * DIM + c4;

    float4 a0 = make_float4(0.f, 0.f, 0.f, 0.f);
    float4 a1 = make_float4(0.f, 0.f, 0.f, 0.f);
    float4 a2 = make_float4(0.f, 0.f, 0.f, 0.f);
    float4 a3 = make_float4(0.f, 0.f, 0.f, 0.f);
    int cur = sb[rg];

    #define FLUSH_ACC() do {                                             \
        float fx = (a0.x + a1.x) + (a2.x + a3.x);                        \
        float fy = (a0.y + a1.y) + (a2.y + a3.y);                        \
        float fz = (a0.z + a1.z) + (a2.z + a3.z);                        \
        float fw = (a0.w + a1.w) + (a2.w + a3.w);                        \
        float* op = out + (size_t)cur * DIM + c4;                        \
        atomicAdd(op + 0, fx); atomicAdd(op + 1, fy);                    \
        atomicAdd(op + 2, fz); atomicAdd(op + 3, fw);                    \
        a0 = a1 = a2 = a3 = make_float4(0.f, 0.f, 0.f, 0.f);             \
    } while (0)

    #pragma unroll 1
    for (int j = rg; j < CHUNK; j += 16) {
        if (sb[j + 12] == cur) {
            float w0 = sw[j], w1 = sw[j + 4], w2 = sw[j + 8], w3 = sw[j + 12];
            float4 v0 = *(const float4*)(xp0 + (size_t)j * DIM);
            float4 v1 = *(const float4*)(xp0 + (size_t)(j + 4) * DIM);
            float4 v2 = *(const float4*)(xp0 + (size_t)(j + 8) * DIM);
            float4 v3 = *(const float4*)(xp0 + (size_t)(j + 12) * DIM);
            a0.x = fmaf(w0, v0.x, a0.x); a0.y = fmaf(w0, v0.y, a0.y);
            a0.z = fmaf(w0, v0.z, a0.z); a0.w = fmaf(w0, v0.w, a0.w);
            a1.x = fmaf(w1, v1.x, a1.x); a1.y = fmaf(w1, v1.y, a1.y);
            a1.z = fmaf(w1, v1.z, a1.z); a1.w = fmaf(w1, v1.w, a1.w);
            a2.x = fmaf(w2, v2.x, a2.x); a2.y = fmaf(w2, v2.y, a2.y);
            a2.z = fmaf(w2, v2.z, a2.z); a2.w = fmaf(w2, v2.w, a2.w);
            a3.x = fmaf(w3, v3.x, a3.x); a3.y = fmaf(w3, v3.y, a3.y);
            a3.z = fmaf(w3, v3.z, a3.z); a3.w = fmaf(w3, v3.w, a3.w);
        } else {
            #pragma unroll
            for (int t = 0; t < 4; t++) {
                int jj = j + 4 * t;
                int b = sb[jj];
                if (b != cur) { FLUSH_ACC(); cur = b; }
                float w = sw[jj];
                float4 v = *(const float4*)(xp0 + (size_t)jj * DIM);
                a0.x = fmaf(w, v.x, a0.x); a0.y = fmaf(w, v.y, a0.y);
                a0.z = fmaf(w, v.z, a0.z); a0.w = fmaf(w, v.w, a0.w);
            }
        }
    }
    FLUSH_ACC();
    #undef FLUSH_ACC
}

// ---------------------------------------------------------------------------
extern "C" void kernel_launch(void* const* d_in, const int* in_sizes, int n_in,
                              void* d_out, int out_size) {
    const float* x     = (const float*)d_in[0];
    const int*   batch = (const int*)d_in[1];
    // d_in[2] = num_graphs (constant 2048, unused)
    const float* W1 = (const float*)d_in[3];
    const float* b1 = (const float*)d_in[4];
    const float* W2 = (const float*)d_in[5];
    const float* b2 = (const float*)d_in[6];
    float* out = (float*)d_out;

    cudaFuncSetAttribute(score_kernel, cudaFuncAttributeMaxDynamicSharedMemorySize, SMEM_BYTES);
    score_kernel<<<SGRID, 256, SMEM_BYTES>>>(x, W1, b1, W2, b2);
    stats_kernel<<<NGRAPH, 256>>>(batch, out);
    stream_pool<<<PBLK, 256>>>(batch, x, out);
}

// round 17
// speedup vs baseline: 1.4737x; 1.0313x over previous
#include <cuda_runtime.h>
#include <cuda_fp16.h>
#include <cstdint>

#define N_NODES 262144
#define DIM     256
#define HID     128
#define NGRAPH  2048
#define NTILES  2048          // N_NODES / 128
#define SGRID   304           // 2 CTAs per SM
#define CHUNK   256           // rows per stream_pool block
#define PBLK    (N_NODES / CHUNK)   // 1024

// smem layout for score kernel (fp16 fragments)
#define WSF_BYTES   65536     // uint32 wsf[16 ks][16 nt][32 lanes][2]  (half2 pairs)
#define XS_OFF      65536     // uint32 xs[2][128][20] = 20480 B (16 data half2 + pad4)
#define B1F_OFF     86016     // float b1f[16][32][2] = 4096 B
#define W2F_OFF     90112     // 4096 B
#define SCP_OFF     94208     // float scp[4][128] = 2048 B
#define SMEM_BYTES  96256

#define XS_STRIDE   20        // uint32 units per row (bank-conflict-free for A frags)

__device__ float g_scores[N_NODES];
__device__ float g_M[NGRAPH];
__device__ float g_invS[NGRAPH];

// ---------------------------------------------------------------------------
__device__ __forceinline__ uint32_t f2h2(float lo, float hi) {
    __half2 h = __floats2half2_rn(lo, hi);
    return *(uint32_t*)&h;
}

__device__ __forceinline__ void mma_f16(float* c,
                                        uint32_t a0, uint32_t a1, uint32_t a2, uint32_t a3,
                                        uint32_t b0, uint32_t b1) {
    asm volatile(
        "mma.sync.aligned.m16n8k16.row.col.f32.f16.f16.f32 "
        "{%0,%1,%2,%3}, {%4,%5,%6,%7}, {%8,%9}, {%0,%1,%2,%3};"
        : "+f"(c[0]), "+f"(c[1]), "+f"(c[2]), "+f"(c[3])
        : "r"(a0), "r"(a1), "r"(a2), "r"(a3), "r"(b0), "r"(b1));
}

__device__ __forceinline__ int lower_bound_i(const int* __restrict__ b, int n, int key) {
    int lo = 0, hi = n;
    while (lo < hi) {
        int mid = (lo + hi) >> 1;
        if (b[mid] < key) lo = mid + 1; else hi = mid;
    }
    return lo;
}
__device__ __forceinline__ float warp_max(float v) {
    #pragma unroll
    for (int o = 16; o; o >>= 1) v = fmaxf(v, __shfl_xor_sync(0xffffffffu, v, o));
    return v;
}
__device__ __forceinline__ float warp_sum(float v) {
    #pragma unroll
    for (int o = 16; o; o >>= 1) v += __shfl_xor_sync(0xffffffffu, v, o);
    return v;
}

// ---------------------------------------------------------------------------
// Kernel 1: scores[i] = b2 + sum_j W2[j] * relu(b1[j] + sum_k x[i][k]*W1[k][j])
// fp16 m16n8k16, balanced warp tiling: 8 warps = 2 row-groups x 4 col-groups;
// each warp 64 rows x 32 cols (4 mt x 4 nt, 64 accum regs). Every B-fragment
// LDS.64 feeds 4 MMAs -> block smem traffic 416 KB/tile (-35% vs R16).
// 96 KB smem + <=128 regs -> 2 CTAs/SM for latency hiding.
// ---------------------------------------------------------------------------
__global__ void __launch_bounds__(256, 2)
score_kernel(const float* __restrict__ x,
             const float* __restrict__ W1,
             const float* __restrict__ b1,
             const float* __restrict__ W2,
             const float* __restrict__ b2) {
    extern __shared__ __align__(16) unsigned char smem[];
    uint32_t* wsf = (uint32_t*)smem;                      // [ks][nt][lane][2]
    uint32_t* xs  = (uint32_t*)(smem + XS_OFF);           // [2][128][20]
    float*    b1f = (float*)(smem + B1F_OFF);             // [nt][lane][2]
    float*    w2f = (float*)(smem + W2F_OFF);
    float*    scp = (float*)(smem + SCP_OFF);             // [4][128]

    const int tid  = threadIdx.x;
    const int lane = tid & 31;
    const int warp = tid >> 5;
    const int rg   = warp >> 2;       // row-group 0..1 (64 rows each)
    const int cg   = warp & 3;        // col-group 0..3 (32 cols each)

    // --- stage W1 as fp16 B-fragments for m16n8k16:
    //     b0 = half2(W1[ks*16+2t4][n], W1[ks*16+2t4+1][n])
    //     b1 = half2(W1[ks*16+2t4+8][n], W1[ks*16+2t4+9][n]),  n = nt*8 + l/4
    for (int i = tid; i < 16 * 16 * 32; i += 256) {
        int l = i & 31, nt = (i >> 5) & 15, ks = i >> 9;
        int n  = nt * 8 + (l >> 2);
        int k0 = ks * 16 + 2 * (l & 3);
        wsf[2 * i + 0] = f2h2(W1[k0 * HID + n],       W1[(k0 + 1) * HID + n]);
        wsf[2 * i + 1] = f2h2(W1[(k0 + 8) * HID + n], W1[(k0 + 9) * HID + n]);
    }
    // --- stage b1 / W2 in C-fragment column order: cols nt*8 + 2*(lane&3) {,+1}
    for (int i = tid; i < 16 * 32; i += 256) {
        int l = i & 31, nt = i >> 5;
        int c0 = nt * 8 + 2 * (l & 3);
        b1f[2 * i + 0] = b1[c0];
        b1f[2 * i + 1] = b1[c0 + 1];
        w2f[2 * i + 0] = W2[c0];
        w2f[2 * i + 1] = W2[c0 + 1];
    }
    const float b2v = b2[0];

    const int srow = tid >> 3;        // staging row 0..31 (covers +32q, q=0..3)
    const int scol = (tid & 7) * 4;   // float col offset within 32-wide chunk

    // --- prologue: chunk 0 of first tile into buffer 0 (convert + store)
    {
        int t0 = blockIdx.x;
        if (t0 < NTILES) {
            #pragma unroll
            for (int q = 0; q < 4; q++) {
                int row = srow + 32 * q;
                float4 v = *(const float4*)(x + (size_t)(t0 * 128 + row) * DIM + scol);
                uint2 h = make_uint2(f2h2(v.x, v.y), f2h2(v.z, v.w));
                *(uint2*)(xs + row * XS_STRIDE + (scol >> 1)) = h;
            }
        }
    }
    __syncthreads();

    const int rA = rg * 64 + (lane >> 2);     // A-frag base row (mt adds 16*mt)
    const int t4 = lane & 3;

    for (int tile = blockIdx.x; tile < NTILES; tile += SGRID) {
        float c[4][4][4];
        #pragma unroll
        for (int mt = 0; mt < 4; mt++)
            #pragma unroll
            for (int nt = 0; nt < 4; nt++)
                #pragma unroll
                for (int q = 0; q < 4; q++) c[mt][nt][q] = 0.0f;

        #pragma unroll 1
        for (int kc = 0; kc < 8; kc++) {
            // prefetch next chunk (next tile's chunk 0 when kc==7)
            int ptile = (kc < 7) ? tile : (tile + SGRID);
            int pkc   = (kc + 1) & 7;
            bool pv   = (ptile < NTILES);
            float4 pr[4];
            if (pv) {
                #pragma unroll
                for (int q = 0; q < 4; q++) {
                    int row = srow + 32 * q;
                    pr[q] = *(const float4*)(x + (size_t)(ptile * 128 + row) * DIM + pkc * 32 + scol);
                }
            }

            // compute 2 k16-steps from current buffer
            const uint32_t* xb = xs + (kc & 1) * (128 * XS_STRIDE);
            #pragma unroll
            for (int ksl = 0; ksl < 2; ksl++) {
                const int cb = ksl * 8 + t4;          // uint32 col base
                const int ks = kc * 2 + ksl;

                // B fragments for this warp's 4 nts (LDS.64 each)
                const uint32_t* wb = wsf + (ks * 512 + lane) * 2;
                uint2 bf[4];
                #pragma unroll
                for (int nt = 0; nt < 4; nt++)
                    bf[nt] = *(const uint2*)(wb + (cg * 4 + nt) * 64);

                // A fragments for 4 mtiles (half2 data, no converts)
                uint32_t a[4][4];
                const uint32_t* rp = xb + rA * XS_STRIDE + cb;
                #pragma unroll
                for (int mt = 0; mt < 4; mt++) {
                    const uint32_t* mp = rp + mt * 16 * XS_STRIDE;
                    a[mt][0] = mp[0];
                    a[mt][1] = mp[8 * XS_STRIDE];
                    a[mt][2] = mp[4];
                    a[mt][3] = mp[8 * XS_STRIDE + 4];
                }

                #pragma unroll
                for (int mt = 0; mt < 4; mt++)
                    #pragma unroll
                    for (int nt = 0; nt < 4; nt++)
                        mma_f16(c[mt][nt], a[mt][0], a[mt][1], a[mt][2], a[mt][3],
                                bf[nt].x, bf[nt].y);
            }

            // convert + store prefetched chunk into other buffer
            if (pv) {
                uint32_t* xd = xs + ((kc + 1) & 1) * (128 * XS_STRIDE);
                #pragma unroll
                for (int q = 0; q < 4; q++) {
                    int row = srow + 32 * q;
                    uint2 h = make_uint2(f2h2(pr[q].x, pr[q].y), f2h2(pr[q].z, pr[q].w));
                    *(uint2*)(xd + row * XS_STRIDE + (scol >> 1)) = h;
                }
            }
            __syncthreads();
        }

        // --- epilogue: bias + relu + dot with W2 over this warp's 32 cols ---
        #pragma unroll
        for (int mt = 0; mt < 4; mt++) {
            float p0 = 0.0f, p8 = 0.0f;
            #pragma unroll
            for (int nt = 0; nt < 4; nt++) {
                int bi = ((cg * 4 + nt) * 32 + lane) * 2;
                float q0 = b1f[bi], q1 = b1f[bi + 1];
                float w0 = w2f[bi], w1 = w2f[bi + 1];
                p0 += fmaxf(c[mt][nt][0] + q0, 0.0f) * w0 + fmaxf(c[mt][nt][1] + q1, 0.0f) * w1;
                p8 += fmaxf(c[mt][nt][2] + q0, 0.0f) * w0 + fmaxf(c[mt][nt][3] + q1, 0.0f) * w1;
            }
            p0 += __shfl_xor_sync(0xffffffffu, p0, 1);
            p0 += __shfl_xor_sync(0xffffffffu, p0, 2);
            p8 += __shfl_xor_sync(0xffffffffu, p8, 1);
            p8 += __shfl_xor_sync(0xffffffffu, p8, 2);
            if ((lane & 3) == 0) {
                int row = rg * 64 + mt * 16 + (lane >> 2);
                scp[cg * 128 + row]     = p0;
                scp[cg * 128 + row + 8] = p8;
            }
        }
        __syncthreads();
        if (tid < 128)
            g_scores[tile * 128 + tid] =
                scp[tid] + scp[128 + tid] + scp[256 + tid] + scp[384 + tid] + b2v;
        __syncthreads();
    }
}

// ---------------------------------------------------------------------------
// Kernel 2: per-graph softmax stats (max, 1/sum_exp); also zero out[].
// ---------------------------------------------------------------------------
__global__ void __launch_bounds__(256)
stats_kernel(const int* __restrict__ batch, float* __restrict__ out) {
    const int g = blockIdx.x;
    const int tid = threadIdx.x;
    const int lane = tid & 31, wid = tid >> 5;
    __shared__ int sse[2];
    __shared__ float red[8];

    out[g * DIM + tid] = 0.0f;

    if (tid < 2) sse[tid] = lower_bound_i(batch, N_NODES, g + tid);
    __syncthreads();
    const int start = sse[0], end = sse[1];

    float m = -1e30f;
    for (int i = start + tid; i < end; i += 256) m = fmaxf(m, g_scores[i]);
    m = warp_max(m);
    if (lane == 0) red[wid] = m;
    __syncthreads();
    if (wid == 0) {
        float v = (lane < 8) ? red[lane] : -1e30f;
        v = warp_max(v);
        if (lane == 0) red[0] = v;
    }
    __syncthreads();
    const float M = red[0];
    __syncthreads();

    float s = 0.0f;
    for (int i = start + tid; i < end; i += 256) s += __expf(g_scores[i] - M);
    s = warp_sum(s);
    if (lane == 0) red[wid] = s;
    __syncthreads();
    if (wid == 0) {
        float v = (lane < 8) ? red[lane] : 0.0f;
        v = warp_sum(v);
        if (lane == 0) {
            g_M[g] = M;
            g_invS[g] = (end > start) ? (1.0f / v) : 0.0f;
        }
    }
}

// ---------------------------------------------------------------------------
// Kernel 3: streaming weighted pooling (uniform chunks, atomic boundary flush).
// Blocks walk x in REVERSE address order for L2 tail reuse from score_kernel.
// ---------------------------------------------------------------------------
__global__ void __launch_bounds__(256)
stream_pool(const int* __restrict__ batch,
            const float* __restrict__ x,
            float* __restrict__ out) {
    const int base = (PBLK - 1 - blockIdx.x) * CHUNK;
    const int tid = threadIdx.x;
    __shared__ __align__(16) float sw[CHUNK];
    __shared__ int sb[CHUNK];

    {
        int r = base + tid;
        int b = batch[r];
        sb[tid] = b;
        sw[tid] = __expf(g_scores[r] - g_M[b]) * g_invS[b];
    }
    __syncthreads();

    const int c4 = (tid & 63) * 4;
    const int rg = tid >> 6;
    const float* xp0 = x + (size_t)base * DIM + c4;

    float4 a0 = make_float4(0.f, 0.f, 0.f, 0.f);
    float4 a1 = make_float4(0.f, 0.f, 0.f, 0.f);
    float4 a2 = make_float4(0.f, 0.f, 0.f, 0.f);
    float4 a3 = make_float4(0.f, 0.f, 0.f, 0.f);
    int cur = sb[rg];

    #define FLUSH_ACC() do {                                             \
        float fx = (a0.x + a1.x) + (a2.x + a3.x);                        \
        float fy = (a0.y + a1.y) + (a2.y + a3.y);                        \
        float fz = (a0.z + a1.z) + (a2.z + a3.z);                        \
        float fw = (a0.w + a1.w) + (a2.w + a3.w);                        \
        float* op = out + (size_t)cur * DIM + c4;                        \
        atomicAdd(op + 0, fx); atomicAdd(op + 1, fy);                    \
        atomicAdd(op + 2, fz); atomicAdd(op + 3, fw);                    \
        a0 = a1 = a2 = a3 = make_float4(0.f, 0.f, 0.f, 0.f);             \
    } while (0)

    #pragma unroll 1
    for (int j = rg; j < CHUNK; j += 16) {
        if (sb[j + 12] == cur) {
            float w0 = sw[j], w1 = sw[j + 4], w2 = sw[j + 8], w3 = sw[j + 12];
            float4 v0 = *(const float4*)(xp0 + (size_t)j * DIM);
            float4 v1 = *(const float4*)(xp0 + (size_t)(j + 4) * DIM);
            float4 v2 = *(const float4*)(xp0 + (size_t)(j + 8) * DIM);
            float4 v3 = *(const float4*)(xp0 + (size_t)(j + 12) * DIM);
            a0.x = fmaf(w0, v0.x, a0.x); a0.y = fmaf(w0, v0.y, a0.y);
            a0.z = fmaf(w0, v0.z, a0.z); a0.w = fmaf(w0, v0.w, a0.w);
            a1.x = fmaf(w1, v1.x, a1.x); a1.y = fmaf(w1, v1.y, a1.y);
            a1.z = fmaf(w1, v1.z, a1.z); a1.w = fmaf(w1, v1.w, a1.w);
            a2.x = fmaf(w2, v2.x, a2.x); a2.y = fmaf(w2, v2.y, a2.y);
            a2.z = fmaf(w2, v2.z, a2.z); a2.w = fmaf(w2, v2.w, a2.w);
            a3.x = fmaf(w3, v3.x, a3.x); a3.y = fmaf(w3, v3.y, a3.y);
            a3.z = fmaf(w3, v3.z, a3.z); a3.w = fmaf(w3, v3.w, a3.w);
        } else {
            #pragma unroll
            for (int t = 0; t < 4; t++) {
                int jj = j + 4 * t;
                int b = sb[jj];
                if (b != cur) { FLUSH_ACC(); cur = b; }
                float w = sw[jj];
                float4 v = *(const float4*)(xp0 + (size_t)jj * DIM);
                a0.x = fmaf(w, v.x, a0.x); a0.y = fmaf(w, v.y, a0.y);
                a0.z = fmaf(w, v.z, a0.z); a0.w = fmaf(w, v.w, a0.w);
            }
        }
    }
    FLUSH_ACC();
    #undef FLUSH_ACC
}

// ---------------------------------------------------------------------------
extern "C" void kernel_launch(void* const* d_in, const int* in_sizes, int n_in,
                              void* d_out, int out_size) {
    const float* x     = (const float*)d_in[0];
    const int*   batch = (const int*)d_in[1];
    // d_in[2] = num_graphs (constant 2048, unused)
    const float* W1 = (const float*)d_in[3];
    const float* b1 = (const float*)d_in[4];
    const float* W2 = (const float*)d_in[5];
    const float* b2 = (const float*)d_in[6];
    float* out = (float*)d_out;

    cudaFuncSetAttribute(score_kernel, cudaFuncAttributeMaxDynamicSharedMemorySize, SMEM_BYTES);
    score_kernel<<<SGRID, 256, SMEM_BYTES>>>(x, W1, b1, W2, b2);
    stats_kernel<<<NGRAPH, 256>>>(batch, out);
    stream_pool<<<PBLK, 256>>>(batch, x, out);
}